// round 14
// baseline (speedup 1.0000x reference)
#include <cuda_runtime.h>
#include <cuda_bf16.h>

// Single persistent kernel: stable 4-class counting sort + margin adjust +
// fused mean-NLL loss. Output: [data[N,4] | labels[N] | loss] float32.
//
// R14: store-compaction variant of R8/R13. Rows are ranked to TILE-LOCAL
// destinations, scattered into a smem staging buffer (scattered STS, cheap),
// then streamed out with fully-coalesced global stores: consecutive staged
// positions map to consecutive addresses within each class segment.

constexpr int TPB = 256;
constexpr int WPB = 8;
constexpr int TILE = 1024;             // rows per tile
constexpr int T_PB_MAX = 12;
constexpr int MAX_TILES = 16384;
constexpr int RESIDENT_BPSM = 6;

__device__ int4 g_tileHist[MAX_TILES];
__device__ int4 g_tileOff[MAX_TILES];
__device__ int4 g_classBase;
__device__ double g_loss;
__device__ unsigned g_histDone;
__device__ unsigned g_scatDone;
__device__ volatile unsigned g_flag;

static __device__ __forceinline__ int4 add4(int4 a, int4 b) {
    return make_int4(a.x + b.x, a.y + b.y, a.z + b.z, a.w + b.w);
}

__global__ void __launch_bounds__(TPB, RESIDENT_BPSM)
fusedKernel(const float* __restrict__ data, const int* __restrict__ label,
            float* __restrict__ outData, float* __restrict__ outLabel,
            float* __restrict__ outLoss, int n, int numTiles) {
    __shared__ unsigned char sClass[T_PB_MAX][TILE / 4];  // 2 bits/row packed
    __shared__ int4 sWarpHist[T_PB_MAX][WPB];
    __shared__ int sDest[TILE];                  // (localDest<<2)|class
    __shared__ float4 staged[TILE];              // tile staging buffer (16KB)
    __shared__ float warpLoss[WPB];
    __shared__ bool sScan;

    int tid = threadIdx.x;
    int w = tid >> 5;
    int lane = tid & 31;

    int t0 = (int)(((long long)blockIdx.x * numTiles) / gridDim.x);
    int t1 = (int)(((long long)(blockIdx.x + 1) * numTiles) / gridDim.x);
    int nt = t1 - t0;
    int nv4 = n >> 2;

    // ---------------- Phase 1: labels -> smem classes + hists ---------------
    for (int s = 0; s < nt; ++s) {
        int tile = t0 + s;
        int vi = (tile * (TILE / 4)) + tid;      // rows 4vi..4vi+3
        int c0 = 0, c1 = 0, c2 = 0, c3 = 0;
        unsigned byte = 0;
        if (vi < nv4) {
            int4 L = __ldcs(reinterpret_cast<const int4*>(label) + vi);
            byte = (unsigned)(L.x | (L.y << 2) | (L.z << 4) | (L.w << 6));
            c0 = (L.x == 0) + (L.y == 0) + (L.z == 0) + (L.w == 0);
            c1 = (L.x == 1) + (L.y == 1) + (L.z == 1) + (L.w == 1);
            c2 = (L.x == 2) + (L.y == 2) + (L.z == 2) + (L.w == 2);
            c3 = (L.x == 3) + (L.y == 3) + (L.z == 3) + (L.w == 3);
        }
        sClass[s][tid] = (unsigned char)byte;
#pragma unroll
        for (int off = 16; off > 0; off >>= 1) {
            c0 += __shfl_down_sync(0xffffffffu, c0, off);
            c1 += __shfl_down_sync(0xffffffffu, c1, off);
            c2 += __shfl_down_sync(0xffffffffu, c2, off);
            c3 += __shfl_down_sync(0xffffffffu, c3, off);
        }
        if (lane == 0) sWarpHist[s][w] = make_int4(c0, c1, c2, c3);
    }
    __syncthreads();
    if (tid < nt) {
        int4 sum = make_int4(0, 0, 0, 0);
#pragma unroll
        for (int ww = 0; ww < WPB; ++ww) sum = add4(sum, sWarpHist[tid][ww]);
        g_tileHist[t0 + tid] = sum;
    }

    // ---------------- Grid sync + scan by last-arriving block ---------------
    __threadfence();
    if (tid == 0) {
        unsigned t = atomicAdd(&g_histDone, 1u);
        sScan = (t == gridDim.x - 1);
        if (sScan) g_histDone = 0;
    }
    __syncthreads();

    if (sScan) {
        __shared__ int4 ss[TPB];
        int chunk = (numTiles + TPB - 1) / TPB;
        int start = tid * chunk;
        int end = min(start + chunk, numTiles);
        int4 s = make_int4(0, 0, 0, 0);
        for (int j = start; j < end; ++j) s = add4(s, g_tileHist[j]);
        ss[tid] = s;
        __syncthreads();
        for (int off = 1; off < TPB; off <<= 1) {
            int4 v = ss[tid];
            if (tid >= off) v = add4(v, ss[tid - off]);
            __syncthreads();
            ss[tid] = v;
            __syncthreads();
        }
        int4 incl = ss[tid];
        int4 tot = ss[TPB - 1];
        int4 run;
        run.x = (incl.x - s.x);
        run.y = (incl.y - s.y) + tot.x;
        run.z = (incl.z - s.z) + tot.x + tot.y;
        run.w = (incl.w - s.w) + tot.x + tot.y + tot.z;
        for (int j = start; j < end; ++j) {
            int4 h = g_tileHist[j];
            g_tileOff[j] = run;
            run = add4(run, h);
        }
        if (tid == 0) {
            g_classBase = make_int4(0, tot.x, tot.x + tot.y,
                                    tot.x + tot.y + tot.z);
            g_loss = 0.0;
        }
        __syncthreads();
        __threadfence();
        if (tid == 0) g_flag = 1;
    } else {
        if (tid == 0) {
            while (g_flag == 0) __nanosleep(64);
        }
        __syncthreads();
        __threadfence();
    }

    // ---------------- Phase 2: staged compaction scatter --------------------
    int4 cb = g_classBase;
    float lsum = 0.0f;

    for (int s = 0; s < nt; ++s) {
        int tile = t0 + s;

        // ---- Stage A: rank rows to tile-LOCAL destinations ------------------
        {
            // tile totals + this-warp prefix within tile
            int tc0 = 0, tc1 = 0, tc2 = 0, tc3 = 0;
            int wb0 = 0, wb1 = 0, wb2 = 0, wb3 = 0;
#pragma unroll
            for (int ww = 0; ww < WPB; ++ww) {
                int4 h = sWarpHist[s][ww];
                if (ww < w) { wb0 += h.x; wb1 += h.y; wb2 += h.z; wb3 += h.w; }
                tc0 += h.x; tc1 += h.y; tc2 += h.z; tc3 += h.w;
            }
            // local class bases within the tile
            int base0 = wb0;
            int base1 = tc0 + wb1;
            int base2 = tc0 + tc1 + wb2;
            int base3 = tc0 + tc1 + tc2 + wb3;

            unsigned byte = sClass[s][tid];
            int c0 = byte & 3, c1 = (byte >> 2) & 3;
            int c2 = (byte >> 4) & 3, c3 = (byte >> 6) & 3;
            unsigned cnt = (1u << (8 * c0)) + (1u << (8 * c1)) +
                           (1u << (8 * c2)) + (1u << (8 * c3));
            unsigned incl = cnt;
#pragma unroll
            for (int off = 1; off < 32; off <<= 1) {
                unsigned v = __shfl_up_sync(0xffffffffu, incl, off);
                if (lane >= off) incl += v;
            }
            unsigned excl = incl - cnt;
            base0 += excl & 0xff;
            base1 += (excl >> 8) & 0xff;
            base2 += (excl >> 16) & 0xff;
            base3 += (excl >> 24) & 0xff;

            int4 dpk;
            int* dv = &dpk.x;
#pragma unroll
            for (int k = 0; k < 4; ++k) {
                int c = (k == 0) ? c0 : (k == 1) ? c1 : (k == 2) ? c2 : c3;
                int dest;
                if (c == 0) dest = base0++;
                else if (c == 1) dest = base1++;
                else if (c == 2) dest = base2++;
                else dest = base3++;
                dv[k] = (dest << 2) | c;
            }
            reinterpret_cast<int4*>(sDest)[tid] = dpk;
        }
        __syncwarp();

        // ---- Stage B: coalesced loads (MLP=4), adjust+loss, STS to staged ---
        {
            int rowT = w * 128 + lane;
            int idx0 = tile * TILE + rowT;
            const float4* dp = reinterpret_cast<const float4*>(data);

            float4 r0, r1, r2, r3;
            r0 = r1 = r2 = r3 = make_float4(0.f, 0.f, 0.f, 0.f);
            if (idx0 < n)       r0 = __ldcs(dp + idx0);
            if (idx0 + 32 < n)  r1 = __ldcs(dp + idx0 + 32);
            if (idx0 + 64 < n)  r2 = __ldcs(dp + idx0 + 64);
            if (idx0 + 96 < n)  r3 = __ldcs(dp + idx0 + 96);

            int d0 = sDest[rowT], d1 = sDest[rowT + 32];
            int d2 = sDest[rowT + 64], d3 = sDest[rowT + 96];

#pragma unroll
            for (int k = 0; k < 4; ++k) {
                if (idx0 + k * 32 >= n) break;
                float4 r = (k == 0) ? r0 : (k == 1) ? r1 : (k == 2) ? r2 : r3;
                int dpacked = (k == 0) ? d0 : (k == 1) ? d1
                            : (k == 2) ? d2 : d3;
                int c = dpacked & 3;

                float v = (c == 0) ? r.x : (c == 1) ? r.y
                        : (c == 2) ? r.z : r.w;
                float adj = (v > 0.0f) ? v * (1.0f / 4.00001f) - 0.5f
                                       : v * 4.00001f - 0.5f;
                if (c == 0) r.x = adj; else if (c == 1) r.y = adj;
                else if (c == 2) r.z = adj; else r.w = adj;

                // no max-subtraction: inputs ~N(0,1) -> exp cannot overflow
                float e = __expf(r.x) + __expf(r.y) +
                          __expf(r.z) + __expf(r.w);
                lsum += __logf(e) - adj;               // -log p[true]

                staged[dpacked >> 2] = r;              // scattered STS (cheap)
            }
        }
        __syncthreads();

        // ---- Stage C: coalesced copy-out + analytic label fill --------------
        {
            // recompute local class boundaries (cheap; avoids live regs in B)
            int tc0 = 0, tc1 = 0, tc2 = 0;
#pragma unroll
            for (int ww = 0; ww < WPB; ++ww) {
                int4 h = sWarpHist[s][ww];
                tc0 += h.x; tc1 += h.y; tc2 += h.z;
            }
            int lb1 = tc0, lb2 = tc0 + tc1, lb3 = lb2 + tc2;
            int4 to = g_tileOff[tile];
            int tileValid = min(TILE, n - tile * TILE);

#pragma unroll
            for (int k = 0; k < 4; ++k) {
                int j = tid + k * TPB;
                if (j < tileValid) {
                    float4 r = staged[j];
                    int c = (j >= lb1) + (j >= lb2) + (j >= lb3);
                    int lb = (c == 0) ? 0 : (c == 1) ? lb1
                           : (c == 2) ? lb2 : lb3;
                    int gb = (c == 0) ? to.x : (c == 1) ? to.y
                           : (c == 2) ? to.z : to.w;
                    __stcs(reinterpret_cast<float4*>(outData) + gb + (j - lb), r);
                }
            }

            // analytic sorted-label fill (streaming float4)
            int p = tile * TILE + tid * 4;
            if (p < n) {
                float4 o;
                o.x = (float)((p     >= cb.y) + (p     >= cb.z) + (p     >= cb.w));
                o.y = (float)((p + 1 >= cb.y) + (p + 1 >= cb.z) + (p + 1 >= cb.w));
                o.z = (float)((p + 2 >= cb.y) + (p + 2 >= cb.z) + (p + 2 >= cb.w));
                o.w = (float)((p + 3 >= cb.y) + (p + 3 >= cb.z) + (p + 3 >= cb.w));
                __stcs(reinterpret_cast<float4*>(outLabel) + (p >> 2), o);
            }
        }
        __syncthreads();   // staged reused next tile
    }

    // ---------------- loss reduce + final scalar ----------------------------
#pragma unroll
    for (int off = 16; off > 0; off >>= 1)
        lsum += __shfl_down_sync(0xffffffffu, lsum, off);
    if (lane == 0) warpLoss[w] = lsum;
    __syncthreads();
    if (tid == 0) {
        double sum = 0.0;
#pragma unroll
        for (int ww = 0; ww < WPB; ++ww) sum += (double)warpLoss[ww];
        atomicAdd(&g_loss, sum);
    }

    __threadfence();
    __shared__ bool isLast;
    if (tid == 0) {
        unsigned t = atomicAdd(&g_scatDone, 1u);
        isLast = (t == gridDim.x - 1);
    }
    __syncthreads();
    if (isLast && tid == 0) {
        g_scatDone = 0;
        g_flag = 0;
        double L = *((volatile double*)&g_loss);
        outLoss[0] = (float)(L / (double)n);
    }
}

extern "C" void kernel_launch(void* const* d_in, const int* in_sizes, int n_in,
                              void* d_out, int out_size) {
    const float* data = (const float*)d_in[0];
    const int* label = (const int*)d_in[1];
    float* out = (float*)d_out;
    int n = in_sizes[1];

    int sms = 148;
    cudaDeviceGetAttribute(&sms, cudaDevAttrMultiProcessorCount, 0);

    int numTiles = (n + TILE - 1) / TILE;
    int grid = sms * RESIDENT_BPSM;
    if (grid > numTiles) grid = numTiles;
    int minGrid = (numTiles + T_PB_MAX - 1) / T_PB_MAX;
    if (grid < minGrid) grid = minGrid;

    fusedKernel<<<grid, TPB>>>(data, label, out, out + (size_t)n * 4,
                               out + (size_t)n * 5, n, numTiles);
}

// round 15
// speedup vs baseline: 1.3387x; 1.3387x over previous
#include <cuda_runtime.h>
#include <cuda_bf16.h>

// Single persistent kernel: stable 4-class counting sort + margin adjust +
// fused mean-NLL loss. Output: [data[N,4] | labels[N] | loss] float32.
//
// R15 = R13 hot paths + block-level (not tile-level) global scan:
//   Phase 1: labels -> smem classes + per-warp/per-tile hists; publish ONE
//            per-block histogram.
//   Grid sync: last-arriving block scans gridDim.x block hists (~912, not
//            8192 tiles) -> per-block offsets. 9x less serial dead time.
//   Phase 2: per-tile offsets reconstructed locally from smem tile hists;
//            packed-count warp scan + smem dest exchange + MLP-4 coalesced
//            loads + direct scatter (best measured shape).

constexpr int TPB = 256;
constexpr int WPB = 8;
constexpr int TILE = 1024;             // rows per tile
constexpr int T_PB_MAX = 12;
constexpr int MAX_BLOCKS_G = 4096;
constexpr int RESIDENT_BPSM = 6;

__device__ int4 g_blockHist[MAX_BLOCKS_G];
__device__ int4 g_blockOff[MAX_BLOCKS_G];
__device__ int4 g_classBase;
__device__ double g_loss;
__device__ unsigned g_histDone;
__device__ unsigned g_scatDone;
__device__ volatile unsigned g_flag;

static __device__ __forceinline__ int4 add4(int4 a, int4 b) {
    return make_int4(a.x + b.x, a.y + b.y, a.z + b.z, a.w + b.w);
}

__global__ void __launch_bounds__(TPB, RESIDENT_BPSM)
fusedKernel(const float* __restrict__ data, const int* __restrict__ label,
            float* __restrict__ outData, float* __restrict__ outLabel,
            float* __restrict__ outLoss, int n, int numTiles) {
    __shared__ unsigned char sClass[T_PB_MAX][TILE / 4];  // 2 bits/row packed
    __shared__ int4 sWarpHist[T_PB_MAX][WPB];
    __shared__ int4 sTileHist[T_PB_MAX];
    __shared__ int sDest[TILE];                           // (dest<<2)|class
    __shared__ float warpLoss[WPB];
    __shared__ bool sScan;

    int tid = threadIdx.x;
    int w = tid >> 5;
    int lane = tid & 31;

    int t0 = (int)(((long long)blockIdx.x * numTiles) / gridDim.x);
    int t1 = (int)(((long long)(blockIdx.x + 1) * numTiles) / gridDim.x);
    int nt = t1 - t0;
    int nv4 = n >> 2;

    // ---------------- Phase 1: labels -> smem classes + hists ---------------
    for (int s = 0; s < nt; ++s) {
        int tile = t0 + s;
        int vi = (tile * (TILE / 4)) + tid;          // rows 4vi..4vi+3
        int c0 = 0, c1 = 0, c2 = 0, c3 = 0;
        unsigned byte = 0;
        if (vi < nv4) {
            int4 L = __ldcs(reinterpret_cast<const int4*>(label) + vi);
            byte = (unsigned)(L.x | (L.y << 2) | (L.z << 4) | (L.w << 6));
            c0 = (L.x == 0) + (L.y == 0) + (L.z == 0) + (L.w == 0);
            c1 = (L.x == 1) + (L.y == 1) + (L.z == 1) + (L.w == 1);
            c2 = (L.x == 2) + (L.y == 2) + (L.z == 2) + (L.w == 2);
            c3 = (L.x == 3) + (L.y == 3) + (L.z == 3) + (L.w == 3);
        }
        sClass[s][tid] = (unsigned char)byte;
#pragma unroll
        for (int off = 16; off > 0; off >>= 1) {
            c0 += __shfl_down_sync(0xffffffffu, c0, off);
            c1 += __shfl_down_sync(0xffffffffu, c1, off);
            c2 += __shfl_down_sync(0xffffffffu, c2, off);
            c3 += __shfl_down_sync(0xffffffffu, c3, off);
        }
        if (lane == 0) sWarpHist[s][w] = make_int4(c0, c1, c2, c3);
    }
    __syncthreads();
    if (tid < nt) {                                  // per-tile totals
        int4 sum = make_int4(0, 0, 0, 0);
#pragma unroll
        for (int ww = 0; ww < WPB; ++ww) sum = add4(sum, sWarpHist[tid][ww]);
        sTileHist[tid] = sum;
    }
    __syncthreads();
    if (tid == 0) {                                  // per-BLOCK total
        int4 bsum = make_int4(0, 0, 0, 0);
        for (int s = 0; s < nt; ++s) bsum = add4(bsum, sTileHist[s]);
        g_blockHist[blockIdx.x] = bsum;
    }

    // ---------------- Grid sync + block-level scan by last block ------------
    __threadfence();
    if (tid == 0) {
        unsigned t = atomicAdd(&g_histDone, 1u);
        sScan = (t == gridDim.x - 1);
        if (sScan) g_histDone = 0;                   // reset for graph replay
    }
    __syncthreads();

    if (sScan) {
        __shared__ int4 ss[TPB];
        int numB = gridDim.x;
        int chunk = (numB + TPB - 1) / TPB;          // ~4
        int start = tid * chunk;
        int end = min(start + chunk, numB);
        int4 s = make_int4(0, 0, 0, 0);
        for (int j = start; j < end; ++j) s = add4(s, g_blockHist[j]);
        ss[tid] = s;
        __syncthreads();
        for (int off = 1; off < TPB; off <<= 1) {
            int4 v = ss[tid];
            if (tid >= off) v = add4(v, ss[tid - off]);
            __syncthreads();
            ss[tid] = v;
            __syncthreads();
        }
        int4 incl = ss[tid];
        int4 tot = ss[TPB - 1];
        int4 run;
        run.x = (incl.x - s.x);
        run.y = (incl.y - s.y) + tot.x;
        run.z = (incl.z - s.z) + tot.x + tot.y;
        run.w = (incl.w - s.w) + tot.x + tot.y + tot.z;
        for (int j = start; j < end; ++j) {
            int4 h = g_blockHist[j];
            g_blockOff[j] = run;
            run = add4(run, h);
        }
        if (tid == 0) {
            g_classBase = make_int4(0, tot.x, tot.x + tot.y,
                                    tot.x + tot.y + tot.z);
            g_loss = 0.0;
        }
        __syncthreads();
        __threadfence();
        if (tid == 0) g_flag = 1;                    // release
    } else {
        if (tid == 0) {
            while (g_flag == 0) __nanosleep(64);
        }
        __syncthreads();
        __threadfence();                             // acquire
    }

    // ---------------- Phase 2: rank via packed scan, coalesced scatter ------
    int4 cb = g_classBase;
    int4 cur = g_blockOff[blockIdx.x];               // running tile offsets
    float lsum = 0.0f;

    for (int s = 0; s < nt; ++s) {
        int tile = t0 + s;

        // ---- rank this thread's 4 consecutive rows (rows 4*tid..4*tid+3) ---
        {
            int base0 = cur.x, base1 = cur.y, base2 = cur.z, base3 = cur.w;
            for (int ww = 0; ww < w; ++ww) {
                int4 h = sWarpHist[s][ww];
                base0 += h.x; base1 += h.y; base2 += h.z; base3 += h.w;
            }
            unsigned byte = sClass[s][tid];
            int c0 = byte & 3, c1 = (byte >> 2) & 3;
            int c2 = (byte >> 4) & 3, c3 = (byte >> 6) & 3;
            unsigned cnt = (1u << (8 * c0)) + (1u << (8 * c1)) +
                           (1u << (8 * c2)) + (1u << (8 * c3));
            unsigned incl = cnt;
#pragma unroll
            for (int off = 1; off < 32; off <<= 1) {
                unsigned v = __shfl_up_sync(0xffffffffu, incl, off);
                if (lane >= off) incl += v;
            }
            unsigned excl = incl - cnt;
            base0 += excl & 0xff;
            base1 += (excl >> 8) & 0xff;
            base2 += (excl >> 16) & 0xff;
            base3 += (excl >> 24) & 0xff;

            int4 dpk;
            int* dv = &dpk.x;
#pragma unroll
            for (int k = 0; k < 4; ++k) {
                int c = (k == 0) ? c0 : (k == 1) ? c1 : (k == 2) ? c2 : c3;
                int dest;
                if (c == 0) dest = base0++;
                else if (c == 1) dest = base1++;
                else if (c == 2) dest = base2++;
                else dest = base3++;
                dv[k] = (dest << 2) | c;
            }
            reinterpret_cast<int4*>(sDest)[tid] = dpk;
        }
        __syncwarp();

        // ---- coalesced streaming loads (MLP=4) + process + scatter ----------
        {
            int rowT = w * 128 + lane;
            int idx0 = tile * TILE + rowT;
            const float4* dp = reinterpret_cast<const float4*>(data);

            float4 r0, r1, r2, r3;
            r0 = r1 = r2 = r3 = make_float4(0.f, 0.f, 0.f, 0.f);
            if (idx0 < n)       r0 = __ldcs(dp + idx0);
            if (idx0 + 32 < n)  r1 = __ldcs(dp + idx0 + 32);
            if (idx0 + 64 < n)  r2 = __ldcs(dp + idx0 + 64);
            if (idx0 + 96 < n)  r3 = __ldcs(dp + idx0 + 96);

            int d0 = sDest[rowT], d1 = sDest[rowT + 32];
            int d2 = sDest[rowT + 64], d3 = sDest[rowT + 96];

#pragma unroll
            for (int k = 0; k < 4; ++k) {
                if (idx0 + k * 32 >= n) break;
                float4 r = (k == 0) ? r0 : (k == 1) ? r1 : (k == 2) ? r2 : r3;
                int dpacked = (k == 0) ? d0 : (k == 1) ? d1
                            : (k == 2) ? d2 : d3;
                int c = dpacked & 3;
                int dest = dpacked >> 2;

                float v = (c == 0) ? r.x : (c == 1) ? r.y
                        : (c == 2) ? r.z : r.w;
                float adj = (v > 0.0f) ? v * (1.0f / 4.00001f) - 0.5f
                                       : v * 4.00001f - 0.5f;
                if (c == 0) r.x = adj; else if (c == 1) r.y = adj;
                else if (c == 2) r.z = adj; else r.w = adj;

                // no max-subtraction: inputs ~N(0,1) -> exp cannot overflow
                float e = __expf(r.x) + __expf(r.y) +
                          __expf(r.z) + __expf(r.w);
                lsum += __logf(e) - adj;             // -log p[true]

                __stcs(reinterpret_cast<float4*>(outData) + dest, r);
            }
        }

        // ---- analytic sorted-label fill (streaming float4) ------------------
        {
            int p = tile * TILE + tid * 4;
            if (p < n) {
                float4 o;
                o.x = (float)((p     >= cb.y) + (p     >= cb.z) + (p     >= cb.w));
                o.y = (float)((p + 1 >= cb.y) + (p + 1 >= cb.z) + (p + 1 >= cb.w));
                o.z = (float)((p + 2 >= cb.y) + (p + 2 >= cb.z) + (p + 2 >= cb.w));
                o.w = (float)((p + 3 >= cb.y) + (p + 3 >= cb.z) + (p + 3 >= cb.w));
                __stcs(reinterpret_cast<float4*>(outLabel) + (p >> 2), o);
            }
        }

        cur = add4(cur, sTileHist[s]);               // advance to next tile
        __syncwarp();   // protect sDest reuse next tile (warp-private region)
    }

    // ---------------- loss reduce + final scalar ----------------------------
#pragma unroll
    for (int off = 16; off > 0; off >>= 1)
        lsum += __shfl_down_sync(0xffffffffu, lsum, off);
    if (lane == 0) warpLoss[w] = lsum;
    __syncthreads();
    if (tid == 0) {
        double sum = 0.0;
#pragma unroll
        for (int ww = 0; ww < WPB; ++ww) sum += (double)warpLoss[ww];
        atomicAdd(&g_loss, sum);
    }

    __threadfence();
    __shared__ bool isLast;
    if (tid == 0) {
        unsigned t = atomicAdd(&g_scatDone, 1u);
        isLast = (t == gridDim.x - 1);
    }
    __syncthreads();
    if (isLast && tid == 0) {
        g_scatDone = 0;
        g_flag = 0;                                  // reset for next replay
        double L = *((volatile double*)&g_loss);
        outLoss[0] = (float)(L / (double)n);
    }
}

extern "C" void kernel_launch(void* const* d_in, const int* in_sizes, int n_in,
                              void* d_out, int out_size) {
    const float* data = (const float*)d_in[0];
    const int* label = (const int*)d_in[1];
    float* out = (float*)d_out;
    int n = in_sizes[1];

    int sms = 148;
    cudaDeviceGetAttribute(&sms, cudaDevAttrMultiProcessorCount, 0);

    int numTiles = (n + TILE - 1) / TILE;
    int grid = sms * RESIDENT_BPSM;
    if (grid > numTiles) grid = numTiles;
    int minGrid = (numTiles + T_PB_MAX - 1) / T_PB_MAX;
    if (grid < minGrid) grid = minGrid;
    if (grid > MAX_BLOCKS_G) grid = MAX_BLOCKS_G;

    fusedKernel<<<grid, TPB>>>(data, label, out, out + (size_t)n * 4,
                               out + (size_t)n * 5, n, numTiles);
}